// round 1
// baseline (speedup 1.0000x reference)
#include <cuda_runtime.h>
#include <math.h>

#define BB 256      // batch
#define HH 1024     // state size
#define TT 128      // timesteps
#define FF 512      // feature out

// ---------------- scratch (static device arrays; no runtime alloc) ----------
__device__ float g_Wsum[HH * 4 * HH];          // 16 MB : W + U for t>=1
__device__ float g_seq[BB * TT * HH];          // 128 MB: h outputs, layout [B, T, H]
__device__ float g_c[BB * HH];                 // 1 MB  : cell state

// ---------------- helpers ----------------------------------------------------
__device__ __forceinline__ float sigmoidf_(float x) {
    return 1.0f / (1.0f + expf(-x));
}

// ---------------- Wsum = W + U ----------------------------------------------
__global__ void add_weights_kernel(const float* __restrict__ W,
                                   const float* __restrict__ U) {
    int i = blockIdx.x * blockDim.x + threadIdx.x;
    int n = HH * 4 * HH;
    for (; i < n; i += gridDim.x * blockDim.x)
        g_Wsum[i] = W[i] + U[i];
}

// ---------------- fused LSTM step: z = x@A (+ h@Bm) + b ; gates ; c,h update -
// Tile: BM=32 batch rows, BJ=64 h-columns (x4 gates), BK=16. 128 threads.
// Each thread: TM=8 rows x TJ=2 cols x 4 gates = 64 accumulators.
#define SBM 32
#define SBJ 64
#define SBK 16

__global__ __launch_bounds__(128)
void lstm_step_kernel(const float* __restrict__ x,  int ldx,
                      const float* __restrict__ A,              // [H,4H] row-major
                      const float* __restrict__ h,  int ldh,    // may be null
                      const float* __restrict__ Bm,             // may be null
                      const float* __restrict__ bias,           // [4H]
                      const float* __restrict__ c_in,
                      float*       __restrict__ c_out,
                      float*       __restrict__ h_out, int ldo)
{
    __shared__ float Xs[SBK][SBM];
    __shared__ float Ws[4][SBK][SBJ];

    const int tid = threadIdx.x;
    const int jt  = tid & 31;        // 32 column groups; thread covers j = jt, jt+32
    const int mt  = tid >> 5;        // 4 row groups; thread covers rows mt*8..mt*8+7

    const int j0 = blockIdx.x * SBJ;
    const int m0 = blockIdx.y * SBM;

    float acc[4][8][2];
    #pragma unroll
    for (int g = 0; g < 4; ++g)
        #pragma unroll
        for (int i = 0; i < 8; ++i)
            #pragma unroll
            for (int j = 0; j < 2; ++j)
                acc[g][i][j] = 0.0f;

    const int npass = (Bm != nullptr) ? 2 : 1;

    for (int pass = 0; pass < npass; ++pass) {
        const float* Xp = (pass == 0) ? x : h;
        const int    ld = (pass == 0) ? ldx : ldh;
        const float* Wp = (pass == 0) ? A : Bm;

        for (int k0 = 0; k0 < HH; k0 += SBK) {
            __syncthreads();
            // load X tile: BM*BK = 512 floats / 128 threads = 4 each
            #pragma unroll
            for (int r = 0; r < 4; ++r) {
                int idx = tid + r * 128;
                int k = idx & (SBK - 1);
                int m = idx >> 4;
                Xs[k][m] = Xp[(m0 + m) * ld + k0 + k];
            }
            // load W tiles: 4*BK*BJ = 4096 floats / 128 threads = 32 each
            #pragma unroll
            for (int r = 0; r < 32; ++r) {
                int idx = tid + r * 128;
                int j = idx & (SBJ - 1);
                int k = (idx >> 6) & (SBK - 1);
                int g = idx >> 10;
                Ws[g][k][j] = Wp[(k0 + k) * (4 * HH) + g * HH + j0 + j];
            }
            __syncthreads();

            #pragma unroll
            for (int kk = 0; kk < SBK; ++kk) {
                float xf[8];
                #pragma unroll
                for (int i = 0; i < 8; ++i) xf[i] = Xs[kk][mt * 8 + i];
                float wf[4][2];
                #pragma unroll
                for (int g = 0; g < 4; ++g) {
                    wf[g][0] = Ws[g][kk][jt];
                    wf[g][1] = Ws[g][kk][jt + 32];
                }
                #pragma unroll
                for (int g = 0; g < 4; ++g)
                    #pragma unroll
                    for (int i = 0; i < 8; ++i)
                        #pragma unroll
                        for (int j = 0; j < 2; ++j)
                            acc[g][i][j] = fmaf(xf[i], wf[g][j], acc[g][i][j]);
            }
        }
    }

    // epilogue: gates + state update
    #pragma unroll
    for (int j = 0; j < 2; ++j) {
        const int jj = j0 + jt + j * 32;
        const float bi = bias[jj];
        const float bf = bias[HH + jj];
        const float bg = bias[2 * HH + jj];
        const float bo = bias[3 * HH + jj];
        #pragma unroll
        for (int i = 0; i < 8; ++i) {
            const int bb = m0 + mt * 8 + i;
            float zi = acc[0][i][j] + bi;
            float zf = acc[1][i][j] + bf;
            float zg = acc[2][i][j] + bg;
            float zo = acc[3][i][j] + bo;
            float c_old = c_in[bb * HH + jj];
            float c_new = sigmoidf_(zf) * c_old + sigmoidf_(zi) * tanhf(zg);
            float h_new = sigmoidf_(zo) * tanhf(c_new);
            c_out[bb * HH + jj] = c_new;
            h_out[bb * ldo + jj] = h_new;
        }
    }
}

// ---------------- dense emission: out[B*T, F] = seq[B*T, H] @ Wd + bd --------
// BM=64, BN=64, BK=16, 256 threads, TM=4, TN=4 (strided mapping).
#define DBM 64
#define DBN 64
#define DBK 16

__global__ __launch_bounds__(256)
void dense_kernel(const float* __restrict__ Wd,   // [H, F]
                  const float* __restrict__ bd,   // [F]
                  float* __restrict__ out)        // [B*T, F]
{
    __shared__ float Xs[DBK][DBM];
    __shared__ float Wsm[DBK][DBN];

    const int tid = threadIdx.x;
    const int tn  = tid & 15;        // col j = tn + 16*jj
    const int tm  = tid >> 4;        // row m = tm + 16*ii

    const int n0 = blockIdx.x * DBN;
    const int m0 = blockIdx.y * DBM;

    float acc[4][4];
    #pragma unroll
    for (int i = 0; i < 4; ++i)
        #pragma unroll
        for (int j = 0; j < 4; ++j) acc[i][j] = 0.0f;

    for (int k0 = 0; k0 < HH; k0 += DBK) {
        __syncthreads();
        // X tile: 64*16 = 1024 / 256 = 4 each
        #pragma unroll
        for (int r = 0; r < 4; ++r) {
            int idx = tid + r * 256;
            int k = idx & (DBK - 1);
            int m = idx >> 4;
            Xs[k][m] = g_seq[(m0 + m) * HH + k0 + k];
        }
        // W tile: 16*64 = 1024 / 256 = 4 each
        #pragma unroll
        for (int r = 0; r < 4; ++r) {
            int idx = tid + r * 256;
            int n = idx & (DBN - 1);
            int k = idx >> 6;
            Wsm[k][n] = Wd[(k0 + k) * FF + n0 + n];
        }
        __syncthreads();

        #pragma unroll
        for (int kk = 0; kk < DBK; ++kk) {
            float xf[4], wf[4];
            #pragma unroll
            for (int i = 0; i < 4; ++i) xf[i] = Xs[kk][tm + 16 * i];
            #pragma unroll
            for (int j = 0; j < 4; ++j) wf[j] = Wsm[kk][tn + 16 * j];
            #pragma unroll
            for (int i = 0; i < 4; ++i)
                #pragma unroll
                for (int j = 0; j < 4; ++j)
                    acc[i][j] = fmaf(xf[i], wf[j], acc[i][j]);
        }
    }

    #pragma unroll
    for (int i = 0; i < 4; ++i) {
        const int m = m0 + tm + 16 * i;
        #pragma unroll
        for (int j = 0; j < 4; ++j) {
            const int n = n0 + tn + 16 * j;
            out[m * FF + n] = acc[i][j] + bd[n];
        }
    }
}

// ---------------- launch -----------------------------------------------------
extern "C" void kernel_launch(void* const* d_in, const int* in_sizes, int n_in,
                              void* d_out, int out_size)
{
    const float* x0 = (const float*)d_in[0];
    const float* h0 = (const float*)d_in[1];
    const float* c0 = (const float*)d_in[2];
    const float* W  = (const float*)d_in[3];
    const float* U  = (const float*)d_in[4];
    const float* b  = (const float*)d_in[5];
    const float* Wd = (const float*)d_in[6];
    const float* bd = (const float*)d_in[7];
    float* out = (float*)d_out;

    void *p_wsum, *p_seq, *p_c;
    cudaGetSymbolAddress(&p_wsum, g_Wsum);
    cudaGetSymbolAddress(&p_seq, g_seq);
    cudaGetSymbolAddress(&p_c, g_c);
    float* wsum = (float*)p_wsum;
    float* seq  = (float*)p_seq;
    float* cbuf = (float*)p_c;

    // 1) Wsum = W + U
    add_weights_kernel<<<1024, 256>>>(W, U);

    dim3 sgrid(HH / SBJ, BB / SBM);   // 16 x 8 = 128 blocks

    // 2) t = 0: z = x0@W + h0@U + b
    lstm_step_kernel<<<sgrid, 128>>>(x0, HH, W, h0, HH, U, b,
                                     c0, cbuf, seq /* t=0 offset */, TT * HH);

    // 3) t = 1..T-1: z = h@Wsum + b   (x == h)
    for (int t = 1; t < TT; ++t) {
        lstm_step_kernel<<<sgrid, 128>>>(seq + (t - 1) * HH, TT * HH, wsum,
                                         nullptr, 0, nullptr, b,
                                         cbuf, cbuf, seq + t * HH, TT * HH);
    }

    // 4) dense: out[B*T, F] = seq @ Wd + bd
    dim3 dgrid(FF / DBN, (BB * TT) / DBM);  // 8 x 512
    dense_kernel<<<dgrid, 256>>>(Wd, bd, out);
}

// round 3
// speedup vs baseline: 2.5151x; 2.5151x over previous
#include <cuda_runtime.h>
#include <cuda_bf16.h>
#include <math.h>
#include <stdint.h>

#define BB 256
#define HH 1024
#define TT 128
#define FF 512

// GEMM tiling: CTA 64(M) x 128(N), KC=32 per stage, 4 stages, 256 threads (8 warps 2x4)
#define KC 32
#define NSTG 4
#define OFF_AH 0
#define OFF_AL 4096
#define OFF_BH 8192
#define OFF_BL 16384
#define STAGE_BYTES 24576
#define SMEM_TOTAL (NSTG * STAGE_BYTES)   // 98304

// ---------------- device scratch (static, no runtime alloc) ------------------
__device__ __nv_bfloat16 g_wsum_hi[4096 * 1024];   // [n=4j+g][k]
__device__ __nv_bfloat16 g_wsum_lo[4096 * 1024];
__device__ __nv_bfloat16 g_wcat_hi[4096 * 2048];   // t=0: K = [W;U]
__device__ __nv_bfloat16 g_wcat_lo[4096 * 2048];
__device__ __nv_bfloat16 g_wd_hi[512 * 1024];      // [f][k]
__device__ __nv_bfloat16 g_wd_lo[512 * 1024];
__device__ __nv_bfloat16 g_xcat_hi[256 * 2048];    // [b][x0,h0]
__device__ __nv_bfloat16 g_xcat_lo[256 * 2048];
__device__ __nv_bfloat16 g_xa_hi[256 * 1024];      // ping
__device__ __nv_bfloat16 g_xa_lo[256 * 1024];
__device__ __nv_bfloat16 g_xb_hi[256 * 1024];      // pong
__device__ __nv_bfloat16 g_xb_lo[256 * 1024];
__device__ __nv_bfloat16 g_seq_hi[(size_t)BB * TT * HH];  // [b*T+t][k]
__device__ __nv_bfloat16 g_seq_lo[(size_t)BB * TT * HH];
__device__ float g_c[BB * HH];

// ---------------- helpers -----------------------------------------------------
__device__ __forceinline__ uint32_t smem_u32(const void* p) {
    uint32_t a;
    asm("{ .reg .u64 t; cvta.to.shared.u64 t, %1; cvt.u32.u64 %0, t; }" : "=r"(a) : "l"(p));
    return a;
}
__device__ __forceinline__ uint32_t sw64(uint32_t o) { return o ^ ((o >> 3) & 0x30); }
__device__ __forceinline__ float sigm(float x) { return 1.0f / (1.0f + expf(-x)); }

#define CP_ASYNC16(sm, gp) \
    asm volatile("cp.async.cg.shared.global [%0], [%1], 16;" :: "r"(sm), "l"(gp) : "memory")
#define CP_COMMIT() asm volatile("cp.async.commit_group;" ::: "memory")
template <int N>
__device__ __forceinline__ void cp_wait() {
    asm volatile("cp.async.wait_group %0;" :: "n"(N) : "memory");
}

__device__ __forceinline__ void ldsm4(uint32_t* r, uint32_t addr) {
    asm volatile("ldmatrix.sync.aligned.m8n8.x4.shared.b16 {%0,%1,%2,%3}, [%4];"
                 : "=r"(r[0]), "=r"(r[1]), "=r"(r[2]), "=r"(r[3]) : "r"(addr));
}
__device__ __forceinline__ void mma16816(float* c, const uint32_t* a, uint32_t b0, uint32_t b1) {
    asm volatile("mma.sync.aligned.m16n8k16.row.col.f32.bf16.bf16.f32 "
                 "{%0,%1,%2,%3},{%4,%5,%6,%7},{%8,%9},{%0,%1,%2,%3};"
                 : "+f"(c[0]), "+f"(c[1]), "+f"(c[2]), "+f"(c[3])
                 : "r"(a[0]), "r"(a[1]), "r"(a[2]), "r"(a[3]), "r"(b0), "r"(b1));
}

// ---------------- pipelined GEMM mainloop ------------------------------------
// A[m][k] (hi/lo), B[n][k] (hi/lo), both row-major with leading dim ldk.
// Accumulates C += Ah*Bh + Ah*Bl + Al*Bh over nch chunks of KC.
__device__ __forceinline__ void issue_load(uint32_t sbase, int s, int c,
                                           const __nv_bfloat16* Ahi, const __nv_bfloat16* Alo,
                                           int am0,
                                           const __nv_bfloat16* Bhi, const __nv_bfloat16* Blo,
                                           int bn0, int ldk, int tid) {
    const uint32_t st = sbase + s * STAGE_BYTES;
    const int k0 = c * KC;
    const int ar = tid >> 2, ac = tid & 3;
    const size_t ga = (size_t)(am0 + ar) * ldk + k0 + ac * 8;
    const uint32_t sa = sw64((uint32_t)(ar * 64 + ac * 16));
    CP_ASYNC16(st + OFF_AH + sa, Ahi + ga);
    CP_ASYNC16(st + OFF_AL + sa, Alo + ga);
#pragma unroll
    for (int it = 0; it < 2; ++it) {
        const int idx = it * 256 + tid;
        const int br = idx >> 2, bc = idx & 3;
        const size_t gb = (size_t)(bn0 + br) * ldk + k0 + bc * 8;
        const uint32_t sb = sw64((uint32_t)(br * 64 + bc * 16));
        CP_ASYNC16(st + OFF_BH + sb, Bhi + gb);
        CP_ASYNC16(st + OFF_BL + sb, Blo + gb);
    }
    CP_COMMIT();
}

__device__ __forceinline__ void gemm_main(char* smem,
                                          const __nv_bfloat16* Ahi, const __nv_bfloat16* Alo,
                                          int am0,
                                          const __nv_bfloat16* Bhi, const __nv_bfloat16* Blo,
                                          int bn0, int ldk, int nch,
                                          float C[2][4][4]) {
    const uint32_t sbase = smem_u32(smem);
    const int tid = threadIdx.x;
    const int lane = tid & 31, wid = tid >> 5;
    const int wm = wid & 1, wn = wid >> 1;

    issue_load(sbase, 0, 0, Ahi, Alo, am0, Bhi, Blo, bn0, ldk, tid);
    issue_load(sbase, 1, 1, Ahi, Alo, am0, Bhi, Blo, bn0, ldk, tid);
    issue_load(sbase, 2, 2, Ahi, Alo, am0, Bhi, Blo, bn0, ldk, tid);

    const int lrow = lane & 15;
    const int lkb = (lane >> 4) * 16;

    for (int c = 0; c < nch; ++c) {
        const int s = c & (NSTG - 1);
        cp_wait<2>();
        __syncthreads();
        const uint32_t st = sbase + s * STAGE_BYTES;
#pragma unroll
        for (int h = 0; h < 2; ++h) {
            uint32_t ah[2][4], al[2][4], bh[2][4], bl[2][4];
#pragma unroll
            for (int mi = 0; mi < 2; ++mi) {
                const uint32_t off = sw64((uint32_t)((wm * 32 + mi * 16 + lrow) * 64 + h * 32 + lkb));
                ldsm4(ah[mi], st + OFF_AH + off);
                ldsm4(al[mi], st + OFF_AL + off);
            }
#pragma unroll
            for (int nj = 0; nj < 2; ++nj) {
                const uint32_t off = sw64((uint32_t)((wn * 32 + nj * 16 + lrow) * 64 + h * 32 + lkb));
                ldsm4(bh[nj], st + OFF_BH + off);
                ldsm4(bl[nj], st + OFF_BL + off);
            }
#pragma unroll
            for (int mi = 0; mi < 2; ++mi)
#pragma unroll
                for (int nt = 0; nt < 4; ++nt) {
                    const int gsel = nt >> 1, ssel = nt & 1;
                    mma16816(C[mi][nt], ah[mi], bh[gsel][ssel], bh[gsel][ssel + 2]);
                    mma16816(C[mi][nt], ah[mi], bl[gsel][ssel], bl[gsel][ssel + 2]);
                    mma16816(C[mi][nt], al[mi], bh[gsel][ssel], bh[gsel][ssel + 2]);
                }
        }
        if (c + 3 < nch)
            issue_load(sbase, (c + 3) & (NSTG - 1), c + 3, Ahi, Alo, am0, Bhi, Blo, bn0, ldk, tid);
    }
}

// ---------------- fused LSTM step kernel --------------------------------------
// grid (32 n-tiles, 4 m-tiles), 256 threads. B rows gate-interleaved: n = 4*j + g.
__global__ __launch_bounds__(256)
void lstm_step_mma(const __nv_bfloat16* __restrict__ Ahi, const __nv_bfloat16* __restrict__ Alo,
                   const __nv_bfloat16* __restrict__ Bhi, const __nv_bfloat16* __restrict__ Blo,
                   int ldk, int nch,
                   const float* __restrict__ bias, const float* __restrict__ c_in,
                   float* __restrict__ c_out,
                   __nv_bfloat16* __restrict__ xh, __nv_bfloat16* __restrict__ xl,
                   int t) {
    extern __shared__ char smem[];
    float C[2][4][4];
#pragma unroll
    for (int a = 0; a < 2; ++a)
#pragma unroll
        for (int bq = 0; bq < 4; ++bq)
#pragma unroll
            for (int d = 0; d < 4; ++d) C[a][bq][d] = 0.0f;

    const int am0 = blockIdx.y * 64;
    const int bn0 = blockIdx.x * 128;
    gemm_main(smem, Ahi, Alo, am0, Bhi, Blo, bn0, ldk, nch, C);

    const int lane = threadIdx.x & 31, wid = threadIdx.x >> 5;
    const int wm = wid & 1, wn = wid >> 1;
    const bool odd = lane & 1;

#pragma unroll
    for (int mi = 0; mi < 2; ++mi)
#pragma unroll
        for (int nt = 0; nt < 4; ++nt) {
            float* c = C[mi][nt];
            const float t0 = __shfl_xor_sync(0xFFFFFFFFu, c[0], 1);
            const float t1 = __shfl_xor_sync(0xFFFFFFFFu, c[1], 1);
            const float t2 = __shfl_xor_sync(0xFFFFFFFFu, c[2], 1);
            const float t3 = __shfl_xor_sync(0xFFFFFFFFu, c[3], 1);
            float zi, zf, zg, zo;
            int rofs;
            if (!odd) { zi = c[0]; zf = c[1]; zg = t0; zo = t1; rofs = 0; }
            else      { zi = t2;  zf = t3;  zg = c[2]; zo = c[3]; rofs = 8; }
            const int b = am0 + wm * 32 + mi * 16 + (lane >> 2) + rofs;
            const int nbase = bn0 + wn * 32 + nt * 8;
            const int j = (nbase >> 2) + ((lane & 3) >> 1);
            zi += bias[j];
            zf += bias[HH + j];
            zg += bias[2 * HH + j];
            zo += bias[3 * HH + j];
            const float cold = c_in[b * HH + j];
            const float cn = sigm(zf) * cold + sigm(zi) * tanhf(zg);
            const float hn = sigm(zo) * tanhf(cn);
            c_out[b * HH + j] = cn;
            const __nv_bfloat16 hhi = __float2bfloat16(hn);
            const __nv_bfloat16 hlo = __float2bfloat16(hn - __bfloat162float(hhi));
            xh[b * HH + j] = hhi;
            xl[b * HH + j] = hlo;
            const size_t si = ((size_t)b * TT + t) * HH + j;
            g_seq_hi[si] = hhi;
            g_seq_lo[si] = hlo;
        }
}

// ---------------- dense emission ----------------------------------------------
// grid (4 n-tiles, 512 m-tiles): out[m][f] = seq[m] . wd[f] + bd[f]
__global__ __launch_bounds__(256)
void dense_mma(const float* __restrict__ bd, float* __restrict__ out) {
    extern __shared__ char smem[];
    float C[2][4][4];
#pragma unroll
    for (int a = 0; a < 2; ++a)
#pragma unroll
        for (int bq = 0; bq < 4; ++bq)
#pragma unroll
            for (int d = 0; d < 4; ++d) C[a][bq][d] = 0.0f;

    const int am0 = blockIdx.y * 64;
    const int bn0 = blockIdx.x * 128;
    gemm_main(smem, g_seq_hi, g_seq_lo, am0, g_wd_hi, g_wd_lo, bn0, HH, HH / KC, C);

    const int lane = threadIdx.x & 31, wid = threadIdx.x >> 5;
    const int wm = wid & 1, wn = wid >> 1;

#pragma unroll
    for (int mi = 0; mi < 2; ++mi)
#pragma unroll
        for (int nt = 0; nt < 4; ++nt) {
            const float* c = C[mi][nt];
            const int n = bn0 + wn * 32 + nt * 8 + 2 * (lane & 3);
            const int r = am0 + wm * 32 + mi * 16 + (lane >> 2);
            float2 v0 = {c[0] + bd[n], c[1] + bd[n + 1]};
            float2 v1 = {c[2] + bd[n], c[3] + bd[n + 1]};
            *reinterpret_cast<float2*>(out + (size_t)r * FF + n) = v0;
            *reinterpret_cast<float2*>(out + (size_t)(r + 8) * FF + n) = v1;
        }
}

// ---------------- prep kernels -------------------------------------------------
__device__ __forceinline__ void split_w(__nv_bfloat16* hi, __nv_bfloat16* lo, size_t o, float v) {
    const __nv_bfloat16 h = __float2bfloat16(v);
    hi[o] = h;
    lo[o] = __float2bfloat16(v - __bfloat162float(h));
}

// wsum: out[n][k] with n = 4j+g, val = W[k][g*1024+j] + U[k][g*1024+j]
__global__ void prep_wsum(const float* __restrict__ W, const float* __restrict__ U) {
    __shared__ float tl[32][33];
    const int n0 = blockIdx.x * 32, k0 = blockIdx.y * 32;
    const int tx = threadIdx.x, ty = threadIdx.y;
    const int n = n0 + tx;
    const int col = ((n & 3) << 10) | (n >> 2);
    for (int kk = ty; kk < 32; kk += 8)
        tl[tx][kk] = W[(size_t)(k0 + kk) * 4096 + col] + U[(size_t)(k0 + kk) * 4096 + col];
    __syncthreads();
    for (int nn = ty; nn < 32; nn += 8)
        split_w(g_wsum_hi, g_wsum_lo, (size_t)(n0 + nn) * 1024 + k0 + tx, tl[nn][tx]);
}

// wcat: out[n][k2], k2<1024 -> W, else U
__global__ void prep_wcat(const float* __restrict__ W, const float* __restrict__ U) {
    __shared__ float tl[32][33];
    const int n0 = blockIdx.x * 32, k0 = blockIdx.y * 32;
    const int tx = threadIdx.x, ty = threadIdx.y;
    const int n = n0 + tx;
    const int col = ((n & 3) << 10) | (n >> 2);
    const float* S = (k0 < 1024) ? W : U;
    const int kbase = (k0 < 1024) ? k0 : (k0 - 1024);
    for (int kk = ty; kk < 32; kk += 8)
        tl[tx][kk] = S[(size_t)(kbase + kk) * 4096 + col];
    __syncthreads();
    for (int nn = ty; nn < 32; nn += 8)
        split_w(g_wcat_hi, g_wcat_lo, (size_t)(n0 + nn) * 2048 + k0 + tx, tl[nn][tx]);
}

// wd: out[f][k] = Wd[k][f]
__global__ void prep_wd(const float* __restrict__ Wd) {
    __shared__ float tl[32][33];
    const int n0 = blockIdx.x * 32, k0 = blockIdx.y * 32;
    const int tx = threadIdx.x, ty = threadIdx.y;
    for (int kk = ty; kk < 32; kk += 8)
        tl[tx][kk] = Wd[(size_t)(k0 + kk) * 512 + n0 + tx];
    __syncthreads();
    for (int nn = ty; nn < 32; nn += 8)
        split_w(g_wd_hi, g_wd_lo, (size_t)(n0 + nn) * 1024 + k0 + tx, tl[nn][tx]);
}

// xcat: [256][2048] = [x0 | h0], elementwise split
__global__ void prep_xc(const float* __restrict__ x0, const float* __restrict__ h0) {
    const int i = blockIdx.x * blockDim.x + threadIdx.x;
    const int m = i >> 11, k = i & 2047;
    const float v = (k < 1024) ? x0[m * 1024 + k] : h0[m * 1024 + k - 1024];
    split_w(g_xcat_hi, g_xcat_lo, (size_t)i, v);
}

// ---------------- launch --------------------------------------------------------
extern "C" void kernel_launch(void* const* d_in, const int* in_sizes, int n_in,
                              void* d_out, int out_size) {
    const float* x0 = (const float*)d_in[0];
    const float* h0 = (const float*)d_in[1];
    const float* c0 = (const float*)d_in[2];
    const float* W  = (const float*)d_in[3];
    const float* U  = (const float*)d_in[4];
    const float* bi = (const float*)d_in[5];
    const float* Wd = (const float*)d_in[6];
    const float* bd = (const float*)d_in[7];
    float* out = (float*)d_out;

    cudaFuncSetAttribute(lstm_step_mma, cudaFuncAttributeMaxDynamicSharedMemorySize, SMEM_TOTAL);
    cudaFuncSetAttribute(dense_mma, cudaFuncAttributeMaxDynamicSharedMemorySize, SMEM_TOTAL);

    void* p;
    cudaGetSymbolAddress(&p, g_wsum_hi);  __nv_bfloat16* wsh = (__nv_bfloat16*)p;
    cudaGetSymbolAddress(&p, g_wsum_lo);  __nv_bfloat16* wsl = (__nv_bfloat16*)p;
    cudaGetSymbolAddress(&p, g_wcat_hi);  __nv_bfloat16* wch = (__nv_bfloat16*)p;
    cudaGetSymbolAddress(&p, g_wcat_lo);  __nv_bfloat16* wcl = (__nv_bfloat16*)p;
    cudaGetSymbolAddress(&p, g_xcat_hi);  __nv_bfloat16* xch = (__nv_bfloat16*)p;
    cudaGetSymbolAddress(&p, g_xcat_lo);  __nv_bfloat16* xcl = (__nv_bfloat16*)p;
    __nv_bfloat16 *xh[2], *xl[2];
    cudaGetSymbolAddress(&p, g_xa_hi);    xh[0] = (__nv_bfloat16*)p;
    cudaGetSymbolAddress(&p, g_xa_lo);    xl[0] = (__nv_bfloat16*)p;
    cudaGetSymbolAddress(&p, g_xb_hi);    xh[1] = (__nv_bfloat16*)p;
    cudaGetSymbolAddress(&p, g_xb_lo);    xl[1] = (__nv_bfloat16*)p;
    cudaGetSymbolAddress(&p, g_c);        float* cbuf = (float*)p;

    dim3 tb(32, 8);
    prep_wsum<<<dim3(128, 32), tb>>>(W, U);
    prep_wcat<<<dim3(128, 64), tb>>>(W, U);
    prep_wd<<<dim3(16, 32), tb>>>(Wd);
    prep_xc<<<2048, 256>>>(x0, h0);

    dim3 sgrid(32, 4);
    // t = 0: A = [x0,h0] (K=2048), B = [W;U]^T interleaved, c_in = c0, writes xh[0]
    lstm_step_mma<<<sgrid, 256, SMEM_TOTAL>>>(xch, xcl, wch, wcl, 2048, 2048 / KC,
                                              bi, c0, cbuf, xh[0], xl[0], 0);
    // t >= 1: A = h(t-1), B = (W+U)^T interleaved
    for (int t = 1; t < TT; ++t) {
        lstm_step_mma<<<sgrid, 256, SMEM_TOTAL>>>(xh[(t + 1) & 1], xl[(t + 1) & 1],
                                                  wsh, wsl, HH, HH / KC,
                                                  bi, cbuf, cbuf, xh[t & 1], xl[t & 1], t);
    }

    dense_mma<<<dim3(4, 512), 256, SMEM_TOTAL>>>(bd, out);
}

// round 5
// speedup vs baseline: 4.5742x; 1.8187x over previous
#include <cuda_runtime.h>
#include <cuda_fp16.h>
#include <math.h>
#include <stdint.h>

#define BB 256
#define HH 1024
#define TT 128
#define FF 512

// GEMM tiling: CTA 64(M) x 128(N), KC=32 per stage, 4 stages, 256 threads (8 warps 2x4)
#define KC 32
#define NSTG 4
#define OFF_A  0
#define OFF_BH 4096
#define OFF_BL 12288
#define STAGE_BYTES 20480
#define SMEM_TOTAL (NSTG * STAGE_BYTES)   // 81920

// ---------------- device scratch (static, no runtime alloc) ------------------
__device__ __half g_wsum_hi[4096 * 1024];   // [n=4j+g][k]
__device__ __half g_wsum_lo[4096 * 1024];
__device__ __half g_wcat_hi[4096 * 2048];   // t=0: K = [W;U]
__device__ __half g_wcat_lo[4096 * 2048];
__device__ __half g_wd_hi[512 * 1024];      // [f][k]
__device__ __half g_wd_lo[512 * 1024];
__device__ __half g_xcat[256 * 2048];       // [b][x0,h0]
__device__ __half g_xa[256 * 1024];         // ping
__device__ __half g_xb[256 * 1024];         // pong
__device__ __half g_seq[(size_t)BB * TT * HH];  // [b*T+t][k]
__device__ float g_c[BB * HH];

// ---------------- helpers -----------------------------------------------------
__device__ __forceinline__ uint32_t smem_u32(const void* p) {
    uint32_t a;
    asm("{ .reg .u64 t; cvta.to.shared.u64 t, %1; cvt.u32.u64 %0, t; }" : "=r"(a) : "l"(p));
    return a;
}
__device__ __forceinline__ uint32_t sw64(uint32_t o) { return o ^ ((o >> 3) & 0x30); }
__device__ __forceinline__ float sigm(float x) { return 1.0f / (1.0f + expf(-x)); }

#define CP_ASYNC16(sm, gp) \
    asm volatile("cp.async.cg.shared.global [%0], [%1], 16;" :: "r"(sm), "l"(gp) : "memory")
#define CP_COMMIT() asm volatile("cp.async.commit_group;" ::: "memory")
template <int N>
__device__ __forceinline__ void cp_wait() {
    asm volatile("cp.async.wait_group %0;" :: "n"(N) : "memory");
}

__device__ __forceinline__ void ldsm4(uint32_t* r, uint32_t addr) {
    asm volatile("ldmatrix.sync.aligned.m8n8.x4.shared.b16 {%0,%1,%2,%3}, [%4];"
                 : "=r"(r[0]), "=r"(r[1]), "=r"(r[2]), "=r"(r[3]) : "r"(addr));
}
__device__ __forceinline__ void mma16816(float* c, const uint32_t* a, uint32_t b0, uint32_t b1) {
    asm volatile("mma.sync.aligned.m16n8k16.row.col.f32.f16.f16.f32 "
                 "{%0,%1,%2,%3},{%4,%5,%6,%7},{%8,%9},{%0,%1,%2,%3};"
                 : "+f"(c[0]), "+f"(c[1]), "+f"(c[2]), "+f"(c[3])
                 : "r"(a[0]), "r"(a[1]), "r"(a[2]), "r"(a[3]), "r"(b0), "r"(b1));
}

// ---------------- pipelined GEMM mainloop ------------------------------------
// A[m][k] single fp16, B[n][k] hi/lo fp16, row-major, leading dim ldk.
// C += A*Bh + A*Bl over nch chunks of KC.
__device__ __forceinline__ void issue_load(uint32_t sbase, int s, int c,
                                           const __half* A, int am0,
                                           const __half* Bhi, const __half* Blo,
                                           int bn0, int ldk, int tid) {
    const uint32_t st = sbase + s * STAGE_BYTES;
    const int k0 = c * KC;
    const int ar = tid >> 2, ac = tid & 3;
    const size_t ga = (size_t)(am0 + ar) * ldk + k0 + ac * 8;
    const uint32_t sa = sw64((uint32_t)(ar * 64 + ac * 16));
    CP_ASYNC16(st + OFF_A + sa, A + ga);
#pragma unroll
    for (int it = 0; it < 2; ++it) {
        const int idx = it * 256 + tid;
        const int br = idx >> 2, bc = idx & 3;
        const size_t gb = (size_t)(bn0 + br) * ldk + k0 + bc * 8;
        const uint32_t sb = sw64((uint32_t)(br * 64 + bc * 16));
        CP_ASYNC16(st + OFF_BH + sb, Bhi + gb);
        CP_ASYNC16(st + OFF_BL + sb, Blo + gb);
    }
    CP_COMMIT();
}

__device__ __forceinline__ void gemm_main(char* smem,
                                          const __half* A, int am0,
                                          const __half* Bhi, const __half* Blo,
                                          int bn0, int ldk, int nch,
                                          float C[2][4][4]) {
    const uint32_t sbase = smem_u32(smem);
    const int tid = threadIdx.x;
    const int lane = tid & 31, wid = tid >> 5;
    const int wm = wid & 1, wn = wid >> 1;

    issue_load(sbase, 0, 0, A, am0, Bhi, Blo, bn0, ldk, tid);
    issue_load(sbase, 1, 1, A, am0, Bhi, Blo, bn0, ldk, tid);
    issue_load(sbase, 2, 2, A, am0, Bhi, Blo, bn0, ldk, tid);

    const int lrow = lane & 15;
    const int lkb = (lane >> 4) * 16;

    for (int c = 0; c < nch; ++c) {
        const int s = c & (NSTG - 1);
        cp_wait<2>();
        __syncthreads();
        const uint32_t st = sbase + s * STAGE_BYTES;
#pragma unroll
        for (int h = 0; h < 2; ++h) {
            uint32_t ah[2][4], bh[2][4], bl[2][4];
#pragma unroll
            for (int mi = 0; mi < 2; ++mi) {
                const uint32_t off = sw64((uint32_t)((wm * 32 + mi * 16 + lrow) * 64 + h * 32 + lkb));
                ldsm4(ah[mi], st + OFF_A + off);
            }
#pragma unroll
            for (int nj = 0; nj < 2; ++nj) {
                const uint32_t off = sw64((uint32_t)((wn * 32 + nj * 16 + lrow) * 64 + h * 32 + lkb));
                ldsm4(bh[nj], st + OFF_BH + off);
                ldsm4(bl[nj], st + OFF_BL + off);
            }
#pragma unroll
            for (int mi = 0; mi < 2; ++mi)
#pragma unroll
                for (int nt = 0; nt < 4; ++nt) {
                    const int gsel = nt >> 1, ssel = nt & 1;
                    mma16816(C[mi][nt], ah[mi], bh[gsel][ssel], bh[gsel][ssel + 2]);
                    mma16816(C[mi][nt], ah[mi], bl[gsel][ssel], bl[gsel][ssel + 2]);
                }
        }
        if (c + 3 < nch)
            issue_load(sbase, (c + 3) & (NSTG - 1), c + 3, A, am0, Bhi, Blo, bn0, ldk, tid);
    }
}

// ---------------- fused LSTM step kernel --------------------------------------
// grid (32 n-tiles, 4 m-tiles), 256 threads. B rows gate-interleaved: n = 4*j + g.
__global__ __launch_bounds__(256)
void lstm_step_mma(const __half* __restrict__ A,
                   const __half* __restrict__ Bhi, const __half* __restrict__ Blo,
                   int ldk, int nch,
                   const float* __restrict__ bias, const float* __restrict__ c_in,
                   float* __restrict__ c_out,
                   __half* __restrict__ xnext, int t) {
    extern __shared__ char smem[];
    float C[2][4][4];
#pragma unroll
    for (int a = 0; a < 2; ++a)
#pragma unroll
        for (int bq = 0; bq < 4; ++bq)
#pragma unroll
            for (int d = 0; d < 4; ++d) C[a][bq][d] = 0.0f;

    const int am0 = blockIdx.y * 64;
    const int bn0 = blockIdx.x * 128;
    gemm_main(smem, A, am0, Bhi, Blo, bn0, ldk, nch, C);

    const int lane = threadIdx.x & 31, wid = threadIdx.x >> 5;
    const int wm = wid & 1, wn = wid >> 1;
    const bool odd = lane & 1;

#pragma unroll
    for (int mi = 0; mi < 2; ++mi)
#pragma unroll
        for (int nt = 0; nt < 4; ++nt) {
            float* c = C[mi][nt];
            const float t0 = __shfl_xor_sync(0xFFFFFFFFu, c[0], 1);
            const float t1 = __shfl_xor_sync(0xFFFFFFFFu, c[1], 1);
            const float t2 = __shfl_xor_sync(0xFFFFFFFFu, c[2], 1);
            const float t3 = __shfl_xor_sync(0xFFFFFFFFu, c[3], 1);
            float zi, zf, zg, zo;
            int rofs;
            if (!odd) { zi = c[0]; zf = c[1]; zg = t0; zo = t1; rofs = 0; }
            else      { zi = t2;  zf = t3;  zg = c[2]; zo = c[3]; rofs = 8; }
            const int b = am0 + wm * 32 + mi * 16 + (lane >> 2) + rofs;
            const int nbase = bn0 + wn * 32 + nt * 8;
            const int j = (nbase >> 2) + ((lane & 3) >> 1);
            zi += bias[j];
            zf += bias[HH + j];
            zg += bias[2 * HH + j];
            zo += bias[3 * HH + j];
            const float cold = c_in[b * HH + j];
            const float cn = sigm(zf) * cold + sigm(zi) * tanhf(zg);
            const float hn = sigm(zo) * tanhf(cn);
            c_out[b * HH + j] = cn;
            const __half hh = __float2half(hn);
            xnext[b * HH + j] = hh;
            g_seq[((size_t)b * TT + t) * HH + j] = hh;
        }
}

// ---------------- dense emission ----------------------------------------------
// grid (4 n-tiles, 512 m-tiles): out[m][f] = seq[m] . wd[f] + bd[f]
__global__ __launch_bounds__(256)
void dense_mma(const float* __restrict__ bd, float* __restrict__ out) {
    extern __shared__ char smem[];
    float C[2][4][4];
#pragma unroll
    for (int a = 0; a < 2; ++a)
#pragma unroll
        for (int bq = 0; bq < 4; ++bq)
#pragma unroll
            for (int d = 0; d < 4; ++d) C[a][bq][d] = 0.0f;

    const int am0 = blockIdx.y * 64;
    const int bn0 = blockIdx.x * 128;
    gemm_main(smem, g_seq, am0, g_wd_hi, g_wd_lo, bn0, HH, HH / KC, C);

    const int lane = threadIdx.x & 31, wid = threadIdx.x >> 5;
    const int wm = wid & 1, wn = wid >> 1;

#pragma unroll
    for (int mi = 0; mi < 2; ++mi)
#pragma unroll
        for (int nt = 0; nt < 4; ++nt) {
            const float* c = C[mi][nt];
            const int n = bn0 + wn * 32 + nt * 8 + 2 * (lane & 3);
            const int r = am0 + wm * 32 + mi * 16 + (lane >> 2);
            float2 v0 = {c[0] + bd[n], c[1] + bd[n + 1]};
            float2 v1 = {c[2] + bd[n], c[3] + bd[n + 1]};
            *reinterpret_cast<float2*>(out + (size_t)r * FF + n) = v0;
            *reinterpret_cast<float2*>(out + (size_t)(r + 8) * FF + n) = v1;
        }
}

// ---------------- prep kernels -------------------------------------------------
__device__ __forceinline__ void split_w(__half* hi, __half* lo, size_t o, float v) {
    const __half h = __float2half(v);
    hi[o] = h;
    lo[o] = __float2half(v - __half2float(h));
}

// wsum: out[n][k] with n = 4j+g, val = W[k][g*1024+j] + U[k][g*1024+j]
__global__ void prep_wsum(const float* __restrict__ W, const float* __restrict__ U) {
    __shared__ float tl[32][33];
    const int n0 = blockIdx.x * 32, k0 = blockIdx.y * 32;
    const int tx = threadIdx.x, ty = threadIdx.y;
    const int n = n0 + tx;
    const int col = ((n & 3) << 10) | (n >> 2);
    for (int kk = ty; kk < 32; kk += 8)
        tl[tx][kk] = W[(size_t)(k0 + kk) * 4096 + col] + U[(size_t)(k0 + kk) * 4096 + col];
    __syncthreads();
    for (int nn = ty; nn < 32; nn += 8)
        split_w(g_wsum_hi, g_wsum_lo, (size_t)(n0 + nn) * 1024 + k0 + tx, tl[nn][tx]);
}

// wcat: out[n][k2], k2<1024 -> W, else U
__global__ void prep_wcat(const float* __restrict__ W, const float* __restrict__ U) {
    __shared__ float tl[32][33];
    const int n0 = blockIdx.x * 32, k0 = blockIdx.y * 32;
    const int tx = threadIdx.x, ty = threadIdx.y;
    const int n = n0 + tx;
    const int col = ((n & 3) << 10) | (n >> 2);
    const float* S = (k0 < 1024) ? W : U;
    const int kbase = (k0 < 1024) ? k0 : (k0 - 1024);
    for (int kk = ty; kk < 32; kk += 8)
        tl[tx][kk] = S[(size_t)(kbase + kk) * 4096 + col];
    __syncthreads();
    for (int nn = ty; nn < 32; nn += 8)
        split_w(g_wcat_hi, g_wcat_lo, (size_t)(n0 + nn) * 2048 + k0 + tx, tl[nn][tx]);
}

// wd: out[f][k] = Wd[k][f]
__global__ void prep_wd(const float* __restrict__ Wd) {
    __shared__ float tl[32][33];
    const int n0 = blockIdx.x * 32, k0 = blockIdx.y * 32;
    const int tx = threadIdx.x, ty = threadIdx.y;
    for (int kk = ty; kk < 32; kk += 8)
        tl[tx][kk] = Wd[(size_t)(k0 + kk) * 512 + n0 + tx];
    __syncthreads();
    for (int nn = ty; nn < 32; nn += 8)
        split_w(g_wd_hi, g_wd_lo, (size_t)(n0 + nn) * 1024 + k0 + tx, tl[nn][tx]);
}

// xcat: [256][2048] = [x0 | h0]
__global__ void prep_xc(const float* __restrict__ x0, const float* __restrict__ h0) {
    const int i = blockIdx.x * blockDim.x + threadIdx.x;
    const int m = i >> 11, k = i & 2047;
    const float v = (k < 1024) ? x0[m * 1024 + k] : h0[m * 1024 + k - 1024];
    g_xcat[i] = __float2half(v);
}

// ---------------- launch --------------------------------------------------------
extern "C" void kernel_launch(void* const* d_in, const int* in_sizes, int n_in,
                              void* d_out, int out_size) {
    const float* x0 = (const float*)d_in[0];
    const float* h0 = (const float*)d_in[1];
    const float* c0 = (const float*)d_in[2];
    const float* W  = (const float*)d_in[3];
    const float* U  = (const float*)d_in[4];
    const float* bi = (const float*)d_in[5];
    const float* Wd = (const float*)d_in[6];
    const float* bd = (const float*)d_in[7];
    float* out = (float*)d_out;

    static bool attr_done = false;
    if (!attr_done) {
        cudaFuncSetAttribute(lstm_step_mma, cudaFuncAttributeMaxDynamicSharedMemorySize, SMEM_TOTAL);
        cudaFuncSetAttribute(dense_mma, cudaFuncAttributeMaxDynamicSharedMemorySize, SMEM_TOTAL);
        attr_done = true;
    }

    void* p;
    cudaGetSymbolAddress(&p, g_wsum_hi);  __half* wsh = (__half*)p;
    cudaGetSymbolAddress(&p, g_wsum_lo);  __half* wsl = (__half*)p;
    cudaGetSymbolAddress(&p, g_wcat_hi);  __half* wch = (__half*)p;
    cudaGetSymbolAddress(&p, g_wcat_lo);  __half* wcl = (__half*)p;
    cudaGetSymbolAddress(&p, g_xcat);     __half* xc  = (__half*)p;
    __half* xb[2];
    cudaGetSymbolAddress(&p, g_xa);       xb[0] = (__half*)p;
    cudaGetSymbolAddress(&p, g_xb);       xb[1] = (__half*)p;
    cudaGetSymbolAddress(&p, g_c);        float* cbuf = (float*)p;

    dim3 tb(32, 8);
    prep_wsum<<<dim3(128, 32), tb>>>(W, U);
    prep_wcat<<<dim3(128, 64), tb>>>(W, U);
    prep_wd<<<dim3(16, 32), tb>>>(Wd);
    prep_xc<<<2048, 256>>>(x0, h0);

    dim3 sgrid(32, 4);
    // t = 0: A = [x0,h0] (K=2048), B = [W;U]^T interleaved, c_in = c0, writes xb[0]
    lstm_step_mma<<<sgrid, 256, SMEM_TOTAL>>>(xc, wch, wcl, 2048, 2048 / KC,
                                              bi, c0, cbuf, xb[0], 0);
    // t >= 1: A = h(t-1), B = (W+U)^T interleaved
    for (int t = 1; t < TT; ++t) {
        lstm_step_mma<<<sgrid, 256, SMEM_TOTAL>>>(xb[(t + 1) & 1], wsh, wsl, HH, HH / KC,
                                                  bi, cbuf, cbuf, xb[t & 1], t);
    }

    dense_mma<<<dim3(4, 512), 256, SMEM_TOTAL>>>(bd, out);
}